// round 2
// baseline (speedup 1.0000x reference)
#include <cuda_runtime.h>
#include <cuda_bf16.h>

// Problem constants
#define BATCH 2
#define SEQ   2049
#define DMODEL 1024
#define HEADS 16
#define DHEAD 64
#define ROWS (BATCH*SEQ)            // 4098
#define QKV_COLS (3*HEADS*DHEAD)    // 3072

// Scratch (device globals; no allocation allowed)
__device__ float g_xn[ROWS * DMODEL];                 // 16.8 MB
__device__ float g_qkv[ROWS * QKV_COLS];              // 50.3 MB
__device__ float g_q[BATCH*HEADS*SEQ*DHEAD];          // 8.4 MB
__device__ float g_k[BATCH*HEADS*SEQ*DHEAD];
__device__ float g_v[BATCH*HEADS*SEQ*DHEAD];
__device__ float g_attn[ROWS * DMODEL];               // 16.8 MB

// ---------------------------------------------------------------------------
// LayerNorm: one block per row, 256 threads, float4 per thread (1024 = 256*4)
// ---------------------------------------------------------------------------
__global__ __launch_bounds__(256) void ln_kernel(
    const float* __restrict__ x, const float* __restrict__ gamma,
    const float* __restrict__ beta, float* __restrict__ xn)
{
    int row = blockIdx.x;
    int tid = threadIdx.x;
    const float4 v = ((const float4*)(x + (size_t)row * DMODEL))[tid];
    float s  = v.x + v.y + v.z + v.w;
    float ss = v.x*v.x + v.y*v.y + v.z*v.z + v.w*v.w;
    #pragma unroll
    for (int o = 16; o; o >>= 1) {
        s  += __shfl_xor_sync(0xFFFFFFFFu, s,  o);
        ss += __shfl_xor_sync(0xFFFFFFFFu, ss, o);
    }
    __shared__ float sm[8], sm2[8];
    int w = tid >> 5;
    if ((tid & 31) == 0) { sm[w] = s; sm2[w] = ss; }
    __syncthreads();
    float ts = 0.f, tss = 0.f;
    #pragma unroll
    for (int i = 0; i < 8; i++) { ts += sm[i]; tss += sm2[i]; }
    const float inv = 1.0f / DMODEL;
    float mu  = ts * inv;
    float var = tss * inv - mu * mu;
    float r = rsqrtf(var + 1e-5f);
    float4 gv = ((const float4*)gamma)[tid];
    float4 bv = ((const float4*)beta)[tid];
    float4 o;
    o.x = (v.x - mu) * r * gv.x + bv.x;
    o.y = (v.y - mu) * r * gv.y + bv.y;
    o.z = (v.z - mu) * r * gv.z + bv.z;
    o.w = (v.w - mu) * r * gv.w + bv.w;
    ((float4*)(xn + (size_t)row * DMODEL))[tid] = o;
}

// ---------------------------------------------------------------------------
// SGEMM: C[M,N] = A[M,K] @ B[K,N], row-major. BM=BN=128, BK=8, TM=TN=8,
// 256 threads. N must be multiple of 128, K multiple of 8. M guarded.
// ---------------------------------------------------------------------------
__global__ __launch_bounds__(256) void sgemm128(
    const float* __restrict__ A, const float* __restrict__ B,
    float* __restrict__ C, int M, int N, int K)
{
    __shared__ float As[8][128];
    __shared__ float Bs[8][128];
    int tid = threadIdx.x;
    int row0 = blockIdx.y * 128;
    int col0 = blockIdx.x * 128;

    int arow = tid >> 1;            // 0..127
    int acol = (tid & 1) * 4;       // 0 or 4
    int brow = tid >> 5;            // 0..7
    int bcol = (tid & 31) * 4;      // 0..124
    int tx = tid & 15, ty = tid >> 4;

    float acc[8][8];
    #pragma unroll
    for (int i = 0; i < 8; i++)
        #pragma unroll
        for (int j = 0; j < 8; j++) acc[i][j] = 0.f;

    for (int k0 = 0; k0 < K; k0 += 8) {
        float4 av = make_float4(0.f, 0.f, 0.f, 0.f);
        if (row0 + arow < M)
            av = *(const float4*)(A + (size_t)(row0 + arow) * K + k0 + acol);
        As[acol + 0][arow] = av.x;
        As[acol + 1][arow] = av.y;
        As[acol + 2][arow] = av.z;
        As[acol + 3][arow] = av.w;
        float4 bv = *(const float4*)(B + (size_t)(k0 + brow) * N + col0 + bcol);
        *(float4*)(&Bs[brow][bcol]) = bv;
        __syncthreads();
        #pragma unroll
        for (int kk = 0; kk < 8; kk++) {
            float a[8], b[8];
            *(float4*)(a)     = *(const float4*)(&As[kk][ty * 8]);
            *(float4*)(a + 4) = *(const float4*)(&As[kk][ty * 8 + 4]);
            *(float4*)(b)     = *(const float4*)(&Bs[kk][tx * 8]);
            *(float4*)(b + 4) = *(const float4*)(&Bs[kk][tx * 8 + 4]);
            #pragma unroll
            for (int i = 0; i < 8; i++)
                #pragma unroll
                for (int j = 0; j < 8; j++)
                    acc[i][j] += a[i] * b[j];
        }
        __syncthreads();
    }
    #pragma unroll
    for (int i = 0; i < 8; i++) {
        int r = row0 + ty * 8 + i;
        if (r < M) {
            float* cp = C + (size_t)r * N + col0 + tx * 8;
            *(float4*)(cp)     = make_float4(acc[i][0], acc[i][1], acc[i][2], acc[i][3]);
            *(float4*)(cp + 4) = make_float4(acc[i][4], acc[i][5], acc[i][6], acc[i][7]);
        }
    }
}

// ---------------------------------------------------------------------------
// RoPE + head reshape. One thread per (b,h,n,i) with i in [0,32): handles the
// rotate-half pair (i, i+32) for q,k and plain copy for v.
// Output layout: [B, H, N, Dh].
// ---------------------------------------------------------------------------
__global__ __launch_bounds__(256) void rope_reshape(
    const float* __restrict__ qkv, float* __restrict__ gq,
    float* __restrict__ gk, float* __restrict__ gv)
{
    const int total = BATCH * HEADS * SEQ * 32;
    int idx = blockIdx.x * blockDim.x + threadIdx.x;
    if (idx >= total) return;
    int i = idx & 31;
    int t = idx >> 5;
    int n = t % SEQ; t /= SEQ;
    int h = t % HEADS;
    int b = t / HEADS;

    const float* base = qkv + ((size_t)(b * SEQ + n)) * QKV_COLS + h * DHEAD;
    float q1 = base[i],        q2 = base[i + 32];
    float k1 = base[1024 + i], k2 = base[1024 + i + 32];
    float v1 = base[2048 + i], v2 = base[2048 + i + 32];
    float qo1 = q1, qo2 = q2, ko1 = k1, ko2 = k2;
    if (n > 0) {
        float p = (float)(n - 1);
        // inv_freq[i] = 10000^(-i/32) = 2^(-log2(10000)*i/32)
        float invf = exp2f(-13.287712379549449f * ((float)i * (1.0f / 32.0f)));
        float f = p * invf;
        float c = cosf(f), s = sinf(f);
        qo1 = q1 * c - q2 * s;  qo2 = q2 * c + q1 * s;
        ko1 = k1 * c - k2 * s;  ko2 = k2 * c + k1 * s;
    }
    size_t dst = ((size_t)((b * HEADS + h) * SEQ + n)) * DHEAD + i;
    gq[dst] = qo1; gq[dst + 32] = qo2;
    gk[dst] = ko1; gk[dst + 32] = ko2;
    gv[dst] = v1;  gv[dst + 32] = v2;
}

// ---------------------------------------------------------------------------
// Attention: flash-style online softmax. One thread = one query row.
// Block: 128 threads (128 queries). K/V tiles of 32 keys in smem.
// Per-thread score row lives in smem (stride 33 -> conflict-free).
// Output layout: [B, N, H*Dh] so the final GEMM reads it directly.
// ---------------------------------------------------------------------------
__global__ __launch_bounds__(128) void attn_kernel(
    const float* __restrict__ gq, const float* __restrict__ gk,
    const float* __restrict__ gv, float* __restrict__ gattn)
{
    __shared__ float Ks[32][64];
    __shared__ float Vs[32][64];
    __shared__ float Ss[128][33];

    int tid = threadIdx.x;
    int b = blockIdx.z, h = blockIdx.y;
    int qi = blockIdx.x * 128 + tid;
    size_t bh = ((size_t)(b * HEADS + h)) * SEQ * DHEAD;
    bool active = qi < SEQ;

    float qreg[64];
    if (active) {
        #pragma unroll
        for (int d = 0; d < 64; d += 4)
            *(float4*)(qreg + d) = *(const float4*)(gq + bh + (size_t)qi * 64 + d);
    }
    float m = -1e30f, l = 0.f;
    float acc[64];
    #pragma unroll
    for (int d = 0; d < 64; d++) acc[d] = 0.f;

    for (int kt = 0; kt < SEQ; kt += 32) {
        int nvalid = min(32, SEQ - kt);
        // cooperative tile load: 512 float4 per tensor, 4 per thread
        #pragma unroll
        for (int li = 0; li < 4; li++) {
            int fl = tid + li * 128;     // float4 index 0..511
            int kr = fl >> 4;            // key row in tile
            int kc = (fl & 15) * 4;
            if (kt + kr < SEQ) {
                *(float4*)(&Ks[kr][kc]) = *(const float4*)(gk + bh + (size_t)(kt + kr) * 64 + kc);
                *(float4*)(&Vs[kr][kc]) = *(const float4*)(gv + bh + (size_t)(kt + kr) * 64 + kc);
            }
        }
        __syncthreads();
        if (active) {
            float mt = -1e30f;
            for (int j = 0; j < nvalid; j++) {
                float s = 0.f;
                #pragma unroll
                for (int d = 0; d < 64; d += 4) {
                    float4 kv = *(const float4*)(&Ks[j][d]);
                    s += qreg[d] * kv.x + qreg[d+1] * kv.y
                       + qreg[d+2] * kv.z + qreg[d+3] * kv.w;
                }
                s *= 0.125f;   // DIM_HEAD^-0.5
                Ss[tid][j] = s;
                mt = fmaxf(mt, s);
            }
            float newm = fmaxf(m, mt);
            float corr = __expf(m - newm);
            l *= corr;
            #pragma unroll
            for (int d = 0; d < 64; d++) acc[d] *= corr;
            for (int j = 0; j < nvalid; j++) {
                float p = __expf(Ss[tid][j] - newm);
                l += p;
                #pragma unroll
                for (int d = 0; d < 64; d += 4) {
                    float4 vv = *(const float4*)(&Vs[j][d]);
                    acc[d]   += p * vv.x; acc[d+1] += p * vv.y;
                    acc[d+2] += p * vv.z; acc[d+3] += p * vv.w;
                }
            }
            m = newm;
        }
        __syncthreads();
    }
    if (active) {
        float rl = 1.0f / l;
        size_t dst = ((size_t)(b * SEQ + qi)) * DMODEL + h * DHEAD;
        #pragma unroll
        for (int d = 0; d < 64; d += 4) {
            float4 o = make_float4(acc[d] * rl, acc[d+1] * rl, acc[d+2] * rl, acc[d+3] * rl);
            *(float4*)(gattn + dst + d) = o;
        }
    }
}

// ---------------------------------------------------------------------------
// Launch
// ---------------------------------------------------------------------------
static float* sym_addr(const void* sym) {
    void* p = nullptr;
    cudaGetSymbolAddress(&p, sym);
    return (float*)p;
}

extern "C" void kernel_launch(void* const* d_in, const int* in_sizes, int n_in,
                              void* d_out, int out_size)
{
    const float* x     = (const float*)d_in[0];
    const float* gamma = (const float*)d_in[1];
    const float* beta  = (const float*)d_in[2];
    const float* wqkv  = (const float*)d_in[3];
    const float* wout  = (const float*)d_in[4];
    float* out = (float*)d_out;

    float* xn   = sym_addr(g_xn);
    float* qkv  = sym_addr(g_qkv);
    float* q    = sym_addr(g_q);
    float* k    = sym_addr(g_k);
    float* v    = sym_addr(g_v);
    float* attn = sym_addr(g_attn);

    ln_kernel<<<ROWS, 256>>>(x, gamma, beta, xn);
    sgemm128<<<dim3(QKV_COLS / 128, (ROWS + 127) / 128), 256>>>(xn, wqkv, qkv, ROWS, QKV_COLS, DMODEL);
    {
        int total = BATCH * HEADS * SEQ * 32;
        rope_reshape<<<(total + 255) / 256, 256>>>(qkv, q, k, v);
    }
    attn_kernel<<<dim3((SEQ + 127) / 128, HEADS, BATCH), 128>>>(q, k, v, attn);
    sgemm128<<<dim3(DMODEL / 128, (ROWS + 127) / 128), 256>>>(attn, wout, out, ROWS, DMODEL, DMODEL);
}

// round 4
// speedup vs baseline: 2.3382x; 2.3382x over previous
#include <cuda_runtime.h>
#include <cuda_bf16.h>
#include <cstdint>

// Problem constants
#define BATCH 2
#define SEQ   2049
#define SEQP  2080              // SEQ padded to multiple of 32
#define DMODEL 1024
#define HEADS 16
#define DHEAD 64
#define ROWS (BATCH*SEQ)        // 4098
#define QKV_COLS (3*HEADS*DHEAD) // 3072
#define NBH (BATCH*HEADS)       // 32

// ---------------------------------------------------------------------------
// Scratch (device globals; no allocation allowed)
// ---------------------------------------------------------------------------
__device__ float g_xn[ROWS * DMODEL];
__device__ float g_qkv[ROWS * QKV_COLS];
__device__ float g_q[NBH * SEQ * DHEAD];
__device__ float g_k[NBH * SEQ * DHEAD];
__device__ float g_vT[NBH * DHEAD * SEQP];            // V transposed, padded K
__device__ float g_S[(size_t)NBH * SEQ * SEQP];       // scores / probs (545 MB)
__device__ float g_attn[ROWS * DMODEL];
__device__ float g_wqkvT[QKV_COLS * DMODEL];
__device__ float g_woutT[DMODEL * DMODEL];

__device__ __forceinline__ float rtf32(float x) {
    uint32_t u;
    asm("cvt.rna.tf32.f32 %0, %1;" : "=r"(u) : "f"(x));
    return __uint_as_float(u);
}
__device__ __forceinline__ uint32_t f2u(float x) { return __float_as_uint(x); }

// ---------------------------------------------------------------------------
// tf32 warp-MMA GEMM: C[z][M,N] = A[z][M,K] @ B[z][N,K]^T
// A,B K-major row-major. K multiple of 32. Tile 128x128, BK=32.
// 256 threads = 8 warps in 2(m) x 4(n); warp tile 64x32.
// C offset per z: (z/czDiv)*cz1 + (z%czDiv)*cz2
// ---------------------------------------------------------------------------
#define GEMM_SMEM_BYTES (2 * 4096 * 2 * 4)   // A+B, 2 buffers, 4096 floats each

__global__ __launch_bounds__(256) void gemm_tf32_mma(
    const float* __restrict__ A, const float* __restrict__ B, float* __restrict__ C,
    int M, int N, int K, int lda, int ldb, int ldc,
    long long aZ, long long bZ, int czDiv, long long cz1, long long cz2, int roundC)
{
    extern __shared__ float smem[];
    float* As = smem;            // [2][128][32] swizzled
    float* Bs = smem + 8192;     // [2][128][32] swizzled

    const int tid = threadIdx.x;
    const int lane = tid & 31;
    const int wid = tid >> 5;
    const int warp_m = wid >> 2;       // 0..1
    const int warp_n = wid & 3;        // 0..3
    const int g  = lane >> 2;          // 0..7
    const int tg = lane & 3;           // 0..3
    const int swz = g << 2;            // fragment-load swizzle term

    const int row0 = blockIdx.y * 128;
    const int col0 = blockIdx.x * 128;
    const int z = blockIdx.z;

    const float* Az = A + (long long)z * aZ;
    const float* Bz = B + (long long)z * bZ;
    float* Cz = C + (long long)(z / czDiv) * cz1 + (long long)(z % czDiv) * cz2;

    float acc[4][4][4];
    #pragma unroll
    for (int mt = 0; mt < 4; mt++)
        #pragma unroll
        for (int nt = 0; nt < 4; nt++)
            #pragma unroll
            for (int i = 0; i < 4; i++) acc[mt][nt][i] = 0.f;

    const float4 z4 = make_float4(0.f, 0.f, 0.f, 0.f);
    float4 pa[4], pb[4];

    // global tile -> regs
    auto load_tile = [&](int kb) {
        const int k0 = kb << 5;
        #pragma unroll
        for (int i = 0; i < 4; i++) {
            const int idx = tid + (i << 8);
            const int r  = idx >> 3;
            const int c4 = (idx & 7) << 2;
            pa[i] = (row0 + r < M) ? *(const float4*)(Az + (size_t)(row0 + r) * lda + k0 + c4) : z4;
            pb[i] = (col0 + r < N) ? *(const float4*)(Bz + (size_t)(col0 + r) * ldb + k0 + c4) : z4;
        }
    };
    // regs -> smem (XOR swizzle)
    auto store_tile = [&](int buf) {
        float* Ab = As + buf * 4096;
        float* Bb = Bs + buf * 4096;
        #pragma unroll
        for (int i = 0; i < 4; i++) {
            const int idx = tid + (i << 8);
            const int r  = idx >> 3;
            const int c4 = (idx & 7) << 2;
            const int sc = c4 ^ ((r & 7) << 2);
            *(float4*)(Ab + r * 32 + sc) = pa[i];
            *(float4*)(Bb + r * 32 + sc) = pb[i];
        }
    };
    auto compute = [&](int buf) {
        const float* Ab = As + buf * 4096;
        const float* Bb = Bs + buf * 4096;
        #pragma unroll
        for (int kk = 0; kk < 4; kk++) {
            const int c = (kk << 3) + tg;
            uint32_t af[4][4], bf[4][2];
            #pragma unroll
            for (int mt = 0; mt < 4; mt++) {
                const int r  = (warp_m << 6) + (mt << 4) + g;
                af[mt][0] = f2u(Ab[r * 32       + (c ^ swz)]);
                af[mt][1] = f2u(Ab[(r + 8) * 32 + (c ^ swz)]);
                af[mt][2] = f2u(Ab[r * 32       + ((c + 4) ^ swz)]);
                af[mt][3] = f2u(Ab[(r + 8) * 32 + ((c + 4) ^ swz)]);
            }
            #pragma unroll
            for (int nt = 0; nt < 4; nt++) {
                const int n = (warp_n << 5) + (nt << 3) + g;
                bf[nt][0] = f2u(Bb[n * 32 + (c ^ swz)]);
                bf[nt][1] = f2u(Bb[n * 32 + ((c + 4) ^ swz)]);
            }
            #pragma unroll
            for (int mt = 0; mt < 4; mt++)
                #pragma unroll
                for (int nt = 0; nt < 4; nt++) {
                    asm volatile(
                        "mma.sync.aligned.m16n8k8.row.col.f32.tf32.tf32.f32 "
                        "{%0,%1,%2,%3}, {%4,%5,%6,%7}, {%8,%9}, {%0,%1,%2,%3};\n"
                        : "+f"(acc[mt][nt][0]), "+f"(acc[mt][nt][1]),
                          "+f"(acc[mt][nt][2]), "+f"(acc[mt][nt][3])
                        : "r"(af[mt][0]), "r"(af[mt][1]), "r"(af[mt][2]), "r"(af[mt][3]),
                          "r"(bf[nt][0]), "r"(bf[nt][1]));
                }
        }
    };

    const int KB = K >> 5;
    load_tile(0);
    store_tile(0);
    __syncthreads();
    for (int kb = 0; kb < KB; kb++) {
        const int buf = kb & 1;
        if (kb + 1 < KB) load_tile(kb + 1);
        compute(buf);
        if (kb + 1 < KB) store_tile(buf ^ 1);
        __syncthreads();
    }

    // epilogue
    #pragma unroll
    for (int mt = 0; mt < 4; mt++) {
        const int r = row0 + (warp_m << 6) + (mt << 4) + g;
        #pragma unroll
        for (int nt = 0; nt < 4; nt++) {
            const int cc = col0 + (warp_n << 5) + (nt << 3) + (tg << 1);
            float v0 = acc[mt][nt][0], v1 = acc[mt][nt][1];
            float v2 = acc[mt][nt][2], v3 = acc[mt][nt][3];
            if (roundC) { v0 = rtf32(v0); v1 = rtf32(v1); v2 = rtf32(v2); v3 = rtf32(v3); }
            if (r < M) {
                if (cc < N)     Cz[(size_t)r * ldc + cc]     = v0;
                if (cc + 1 < N) Cz[(size_t)r * ldc + cc + 1] = v1;
            }
            if (r + 8 < M) {
                if (cc < N)     Cz[(size_t)(r + 8) * ldc + cc]     = v2;
                if (cc + 1 < N) Cz[(size_t)(r + 8) * ldc + cc + 1] = v3;
            }
        }
    }
}

// ---------------------------------------------------------------------------
// LayerNorm (outputs tf32-rounded)
// ---------------------------------------------------------------------------
__global__ __launch_bounds__(256) void ln_kernel(
    const float* __restrict__ x, const float* __restrict__ gamma,
    const float* __restrict__ beta, float* __restrict__ xn)
{
    int row = blockIdx.x;
    int tid = threadIdx.x;
    const float4 v = ((const float4*)(x + (size_t)row * DMODEL))[tid];
    float s  = v.x + v.y + v.z + v.w;
    float ss = v.x*v.x + v.y*v.y + v.z*v.z + v.w*v.w;
    #pragma unroll
    for (int o = 16; o; o >>= 1) {
        s  += __shfl_xor_sync(0xFFFFFFFFu, s,  o);
        ss += __shfl_xor_sync(0xFFFFFFFFu, ss, o);
    }
    __shared__ float sm[8], sm2[8];
    int w = tid >> 5;
    if ((tid & 31) == 0) { sm[w] = s; sm2[w] = ss; }
    __syncthreads();
    float ts = 0.f, tss = 0.f;
    #pragma unroll
    for (int i = 0; i < 8; i++) { ts += sm[i]; tss += sm2[i]; }
    const float inv = 1.0f / DMODEL;
    float mu  = ts * inv;
    float var = tss * inv - mu * mu;
    float r = rsqrtf(var + 1e-5f);
    float4 gv = ((const float4*)gamma)[tid];
    float4 bv = ((const float4*)beta)[tid];
    float4 o;
    o.x = rtf32((v.x - mu) * r * gv.x + bv.x);
    o.y = rtf32((v.y - mu) * r * gv.y + bv.y);
    o.z = rtf32((v.z - mu) * r * gv.z + bv.z);
    o.w = rtf32((v.w - mu) * r * gv.w + bv.w);
    ((float4*)(xn + (size_t)row * DMODEL))[tid] = o;
}

// ---------------------------------------------------------------------------
// Transpose with tf32 rounding: dst[C,R] = src[R,C]^T
// ---------------------------------------------------------------------------
__global__ __launch_bounds__(256) void transpose_rnd(
    const float* __restrict__ src, float* __restrict__ dst, int R, int C)
{
    __shared__ float t[32][33];
    int c0 = blockIdx.x * 32, r0 = blockIdx.y * 32;
    int x = threadIdx.x, y = threadIdx.y;   // 32 x 8
    #pragma unroll
    for (int i = 0; i < 32; i += 8) {
        int r = r0 + y + i, c = c0 + x;
        if (r < R && c < C) t[y + i][x] = src[(size_t)r * C + c];
    }
    __syncthreads();
    #pragma unroll
    for (int i = 0; i < 32; i += 8) {
        int r = c0 + y + i, c = r0 + x;
        if (r < C && c < R) dst[(size_t)r * R + c] = rtf32(t[x][y + i]);
    }
}

// ---------------------------------------------------------------------------
// RoPE + head reshape. q,k -> [bh, n, 64] rounded; v -> vT [bh, 64, SEQP] rounded
// ---------------------------------------------------------------------------
__global__ __launch_bounds__(256) void rope_reshape(
    const float* __restrict__ qkv, float* __restrict__ gq,
    float* __restrict__ gk, float* __restrict__ gvT)
{
    const int total = NBH * SEQ * 32;
    int idx = blockIdx.x * blockDim.x + threadIdx.x;
    if (idx >= total) return;
    int i = idx & 31;
    int t = idx >> 5;
    int n = t % SEQ; t /= SEQ;
    int h = t % HEADS;
    int b = t / HEADS;
    int bh = b * HEADS + h;

    const float* base = qkv + ((size_t)(b * SEQ + n)) * QKV_COLS + h * DHEAD;
    float q1 = base[i],        q2 = base[i + 32];
    float k1 = base[1024 + i], k2 = base[1024 + i + 32];
    float v1 = base[2048 + i], v2 = base[2048 + i + 32];
    float qo1 = q1, qo2 = q2, ko1 = k1, ko2 = k2;
    if (n > 0) {
        float p = (float)(n - 1);
        float invf = exp2f(-13.287712379549449f * ((float)i * (1.0f / 32.0f)));
        float f = p * invf;
        float c = cosf(f), s = sinf(f);
        qo1 = q1 * c - q2 * s;  qo2 = q2 * c + q1 * s;
        ko1 = k1 * c - k2 * s;  ko2 = k2 * c + k1 * s;
    }
    size_t dst = ((size_t)bh * SEQ + n) * DHEAD + i;
    gq[dst] = rtf32(qo1); gq[dst + 32] = rtf32(qo2);
    gk[dst] = rtf32(ko1); gk[dst + 32] = rtf32(ko2);
    size_t vd = ((size_t)bh * DHEAD + i) * SEQP + n;
    gvT[vd] = rtf32(v1); gvT[vd + (size_t)32 * SEQP] = rtf32(v2);
}

// Zero the K-padding columns of vT (cols SEQ..SEQP-1 for all rows)
__global__ void vt_pad_zero(float* __restrict__ gvT)
{
    int idx = blockIdx.x * blockDim.x + threadIdx.x;
    const int padw = SEQP - SEQ;                 // 31
    const int total = NBH * DHEAD * padw;
    if (idx >= total) return;
    int c = idx % padw;
    int r = idx / padw;
    gvT[(size_t)r * SEQP + SEQ + c] = 0.f;
}

// ---------------------------------------------------------------------------
// Softmax over S rows (length SEQ, stride SEQP); scale 0.125 applied here;
// output normalized probabilities rounded to tf32; pad cols zeroed.
// grid(SEQ, NBH), 256 threads.
// ---------------------------------------------------------------------------
__global__ __launch_bounds__(256) void softmax_kernel(float* __restrict__ S)
{
    const int tid = threadIdx.x;
    float* row = S + ((size_t)blockIdx.y * SEQ + blockIdx.x) * SEQP;

    float vals[9];
    float m = -1e30f;
    #pragma unroll
    for (int j = 0; j < 9; j++) {
        int i = tid + j * 256;
        float v = -1e30f;
        if (i < SEQ) v = row[i] * 0.125f;
        vals[j] = v;
        m = fmaxf(m, v);
    }
    #pragma unroll
    for (int o = 16; o; o >>= 1) m = fmaxf(m, __shfl_xor_sync(0xFFFFFFFFu, m, o));
    __shared__ float sm[8];
    if ((tid & 31) == 0) sm[tid >> 5] = m;
    __syncthreads();
    float gm = -1e30f;
    #pragma unroll
    for (int i = 0; i < 8; i++) gm = fmaxf(gm, sm[i]);

    float lsum = 0.f;
    #pragma unroll
    for (int j = 0; j < 9; j++) {
        int i = tid + j * 256;
        float e = 0.f;
        if (i < SEQ) e = __expf(vals[j] - gm);
        vals[j] = e;
        lsum += e;
    }
    #pragma unroll
    for (int o = 16; o; o >>= 1) lsum += __shfl_xor_sync(0xFFFFFFFFu, lsum, o);
    __shared__ float ssum[8];
    if ((tid & 31) == 0) ssum[tid >> 5] = lsum;
    __syncthreads();
    float gs = 0.f;
    #pragma unroll
    for (int i = 0; i < 8; i++) gs += ssum[i];
    float rinv = 1.0f / gs;

    #pragma unroll
    for (int j = 0; j < 9; j++) {
        int i = tid + j * 256;
        if (i < SEQ) row[i] = rtf32(vals[j] * rinv);
        else if (i < SEQP) row[i] = 0.f;
    }
}

// ---------------------------------------------------------------------------
// Launch
// ---------------------------------------------------------------------------
static float* sym_addr(const void* sym) {
    void* p = nullptr;
    cudaGetSymbolAddress(&p, sym);
    return (float*)p;
}

extern "C" void kernel_launch(void* const* d_in, const int* in_sizes, int n_in,
                              void* d_out, int out_size)
{
    const float* x     = (const float*)d_in[0];
    const float* gamma = (const float*)d_in[1];
    const float* beta  = (const float*)d_in[2];
    const float* wqkv  = (const float*)d_in[3];
    const float* wout  = (const float*)d_in[4];
    float* out = (float*)d_out;

    float* xn    = sym_addr(g_xn);
    float* qkv   = sym_addr(g_qkv);
    float* q     = sym_addr(g_q);
    float* k     = sym_addr(g_k);
    float* vT    = sym_addr(g_vT);
    float* S     = sym_addr(g_S);
    float* attn  = sym_addr(g_attn);
    float* wqkvT = sym_addr(g_wqkvT);
    float* woutT = sym_addr(g_woutT);

    cudaFuncSetAttribute(gemm_tf32_mma, cudaFuncAttributeMaxDynamicSharedMemorySize, GEMM_SMEM_BYTES);

    // 1. LayerNorm (tf32-rounded)
    ln_kernel<<<ROWS, 256>>>(x, gamma, beta, xn);
    // 2. Transpose weights to [N,K] K-major (tf32-rounded)
    transpose_rnd<<<dim3(QKV_COLS / 32, DMODEL / 32), dim3(32, 8)>>>(wqkv, wqkvT, DMODEL, QKV_COLS);
    transpose_rnd<<<dim3(DMODEL / 32, DMODEL / 32), dim3(32, 8)>>>(wout, woutT, DMODEL, DMODEL);
    // 3. QKV = xn @ w_qkv  (M=4098, N=3072, K=1024)
    gemm_tf32_mma<<<dim3(QKV_COLS / 128, (ROWS + 127) / 128, 1), 256, GEMM_SMEM_BYTES>>>(
        xn, wqkvT, qkv, ROWS, QKV_COLS, DMODEL, DMODEL, DMODEL, QKV_COLS,
        0LL, 0LL, 1, 0LL, 0LL, 0);
    // 4. RoPE + reshape (q,k rounded; v transposed+padded)
    {
        int total = NBH * SEQ * 32;
        rope_reshape<<<(total + 255) / 256, 256>>>(qkv, q, k, vT);
        int padtot = NBH * DHEAD * (SEQP - SEQ);
        vt_pad_zero<<<(padtot + 255) / 256, 256>>>(vT);
    }
    // 5. S = Q @ K^T per (b,h)  (M=N=2049, K=64, batched 32)
    gemm_tf32_mma<<<dim3((SEQ + 127) / 128, (SEQ + 127) / 128, NBH), 256, GEMM_SMEM_BYTES>>>(
        q, k, S, SEQ, SEQ, DHEAD, DHEAD, DHEAD, SEQP,
        (long long)SEQ * DHEAD, (long long)SEQ * DHEAD,
        1, (long long)SEQ * SEQP, 0LL, 0);
    // 6. softmax rows (in place, scale, round to tf32, zero pads)
    softmax_kernel<<<dim3(SEQ, NBH), 256>>>(S);
    // 7. O = P @ V per (b,h)  (M=2049, N=64, K=2080) -> attn [B,N,H*Dh]
    gemm_tf32_mma<<<dim3(1, (SEQ + 127) / 128, NBH), 256, GEMM_SMEM_BYTES>>>(
        S, vT, attn, SEQ, DHEAD, SEQP, SEQP, SEQP, DMODEL,
        (long long)SEQ * SEQP, (long long)DHEAD * SEQP,
        HEADS, (long long)SEQ * DMODEL, (long long)DHEAD, 1);
    // 8. out = attn @ w_out  (M=4098, N=1024, K=1024)
    gemm_tf32_mma<<<dim3(DMODEL / 128, (ROWS + 127) / 128, 1), 256, GEMM_SMEM_BYTES>>>(
        attn, woutT, out, ROWS, DMODEL, DMODEL, DMODEL, DMODEL, DMODEL,
        0LL, 0LL, 1, 0LL, 0LL, 0);
}

// round 5
// speedup vs baseline: 4.0028x; 1.7119x over previous
#include <cuda_runtime.h>
#include <cuda_bf16.h>
#include <cstdint>

// Problem constants
#define BATCH 2
#define SEQ   2049
#define SEQP  2112              // keys padded to 33*64 for fused attention
#define DMODEL 1024
#define HEADS 16
#define DHEAD 64
#define ROWS (BATCH*SEQ)        // 4098
#define QKV_COLS (3*HEADS*DHEAD) // 3072
#define NBH (BATCH*HEADS)       // 32
#define NKT 33                  // number of 64-key tiles

// ---------------------------------------------------------------------------
// Scratch (device globals; no allocation allowed)
// ---------------------------------------------------------------------------
__device__ float g_xn[ROWS * DMODEL];
__device__ float g_qkv[ROWS * QKV_COLS];
__device__ float g_q[NBH * SEQ * DHEAD];
__device__ float g_k[NBH * SEQ * DHEAD];
__device__ float g_vT[NBH * DHEAD * SEQP];            // V transposed, padded keys
__device__ float g_attn[ROWS * DMODEL];
__device__ float g_wqkvT[QKV_COLS * DMODEL];
__device__ float g_woutT[DMODEL * DMODEL];

__device__ __forceinline__ float rtf32(float x) {
    uint32_t u;
    asm("cvt.rna.tf32.f32 %0, %1;" : "=r"(u) : "f"(x));
    return __uint_as_float(u);
}
__device__ __forceinline__ uint32_t f2u(float x) { return __float_as_uint(x); }

#define MMA_TF32(acc, a0, a1, a2, a3, b0, b1)                                \
    asm volatile(                                                            \
        "mma.sync.aligned.m16n8k8.row.col.f32.tf32.tf32.f32 "                \
        "{%0,%1,%2,%3}, {%4,%5,%6,%7}, {%8,%9}, {%0,%1,%2,%3};\n"            \
        : "+f"((acc)[0]), "+f"((acc)[1]), "+f"((acc)[2]), "+f"((acc)[3])     \
        : "r"(a0), "r"(a1), "r"(a2), "r"(a3), "r"(b0), "r"(b1))

// ---------------------------------------------------------------------------
// tf32 warp-MMA GEMM: C = A[M,K] @ B[N,K]^T (both K-major). Tile 128x128, BK=32.
// 256 threads = 8 warps in 2(m) x 4(n); warp tile 64x32.
// ---------------------------------------------------------------------------
#define GEMM_SMEM_BYTES (2 * 4096 * 2 * 4)

__global__ __launch_bounds__(256) void gemm_tf32_mma(
    const float* __restrict__ A, const float* __restrict__ B, float* __restrict__ C,
    int M, int N, int K, int lda, int ldb, int ldc)
{
    extern __shared__ float smem[];
    float* As = smem;
    float* Bs = smem + 8192;

    const int tid = threadIdx.x;
    const int lane = tid & 31;
    const int wid = tid >> 5;
    const int warp_m = wid >> 2;
    const int warp_n = wid & 3;
    const int g  = lane >> 2;
    const int tg = lane & 3;
    const int swz = g << 2;

    const int row0 = blockIdx.y * 128;
    const int col0 = blockIdx.x * 128;

    float acc[4][4][4];
    #pragma unroll
    for (int mt = 0; mt < 4; mt++)
        #pragma unroll
        for (int nt = 0; nt < 4; nt++)
            #pragma unroll
            for (int i = 0; i < 4; i++) acc[mt][nt][i] = 0.f;

    const float4 z4 = make_float4(0.f, 0.f, 0.f, 0.f);
    float4 pa[4], pb[4];

    auto load_tile = [&](int kb) {
        const int k0 = kb << 5;
        #pragma unroll
        for (int i = 0; i < 4; i++) {
            const int idx = tid + (i << 8);
            const int r  = idx >> 3;
            const int c4 = (idx & 7) << 2;
            pa[i] = (row0 + r < M) ? *(const float4*)(A + (size_t)(row0 + r) * lda + k0 + c4) : z4;
            pb[i] = (col0 + r < N) ? *(const float4*)(B + (size_t)(col0 + r) * ldb + k0 + c4) : z4;
        }
    };
    auto store_tile = [&](int buf) {
        float* Ab = As + buf * 4096;
        float* Bb = Bs + buf * 4096;
        #pragma unroll
        for (int i = 0; i < 4; i++) {
            const int idx = tid + (i << 8);
            const int r  = idx >> 3;
            const int c4 = (idx & 7) << 2;
            const int sc = c4 ^ ((r & 7) << 2);
            *(float4*)(Ab + r * 32 + sc) = pa[i];
            *(float4*)(Bb + r * 32 + sc) = pb[i];
        }
    };
    auto compute = [&](int buf) {
        const float* Ab = As + buf * 4096;
        const float* Bb = Bs + buf * 4096;
        #pragma unroll
        for (int kk = 0; kk < 4; kk++) {
            const int c = (kk << 3) + tg;
            uint32_t af[4][4], bf[4][2];
            #pragma unroll
            for (int mt = 0; mt < 4; mt++) {
                const int r  = (warp_m << 6) + (mt << 4) + g;
                af[mt][0] = f2u(Ab[r * 32       + (c ^ swz)]);
                af[mt][1] = f2u(Ab[(r + 8) * 32 + (c ^ swz)]);
                af[mt][2] = f2u(Ab[r * 32       + ((c + 4) ^ swz)]);
                af[mt][3] = f2u(Ab[(r + 8) * 32 + ((c + 4) ^ swz)]);
            }
            #pragma unroll
            for (int nt = 0; nt < 4; nt++) {
                const int n = (warp_n << 5) + (nt << 3) + g;
                bf[nt][0] = f2u(Bb[n * 32 + (c ^ swz)]);
                bf[nt][1] = f2u(Bb[n * 32 + ((c + 4) ^ swz)]);
            }
            #pragma unroll
            for (int mt = 0; mt < 4; mt++)
                #pragma unroll
                for (int nt = 0; nt < 4; nt++)
                    MMA_TF32(acc[mt][nt], af[mt][0], af[mt][1], af[mt][2], af[mt][3],
                             bf[nt][0], bf[nt][1]);
        }
    };

    const int KB = K >> 5;
    load_tile(0);
    store_tile(0);
    __syncthreads();
    for (int kb = 0; kb < KB; kb++) {
        const int buf = kb & 1;
        if (kb + 1 < KB) load_tile(kb + 1);
        compute(buf);
        if (kb + 1 < KB) store_tile(buf ^ 1);
        __syncthreads();
    }

    #pragma unroll
    for (int mt = 0; mt < 4; mt++) {
        const int r = row0 + (warp_m << 6) + (mt << 4) + g;
        #pragma unroll
        for (int nt = 0; nt < 4; nt++) {
            const int cc = col0 + (warp_n << 5) + (nt << 3) + (tg << 1);
            if (r < M && cc + 1 < N) {
                *(float2*)(C + (size_t)r * ldc + cc) =
                    make_float2(acc[mt][nt][0], acc[mt][nt][1]);
            }
            if (r + 8 < M && cc + 1 < N) {
                *(float2*)(C + (size_t)(r + 8) * ldc + cc) =
                    make_float2(acc[mt][nt][2], acc[mt][nt][3]);
            }
        }
    }
}

// ---------------------------------------------------------------------------
// Fused flash attention (tf32 mma). Block = 128 queries x one (b,h).
// 256 threads = 8 warps; warp owns 16 query rows. K-tiles of 64 keys.
// ---------------------------------------------------------------------------
#define ATT_SMEM_BYTES ((64*68 + 64*68 + 128*68) * 4)   // sK, sV, sP = 69632 B

__global__ __launch_bounds__(256) void fused_attn(
    const float* __restrict__ gq, const float* __restrict__ gk,
    const float* __restrict__ gvT, float* __restrict__ gattn)
{
    extern __shared__ float sm[];
    float* sK = sm;                 // [64][68] keys x Dh
    float* sV = sm + 64 * 68;       // [64][68] Dh x keys (V^T tile)
    float* sP = sV + 64 * 68;       // [128][68] probs (also Q staging)

    const int tid = threadIdx.x;
    const int lane = tid & 31, wid = tid >> 5;
    const int g = lane >> 2, tg = lane & 3;
    const int m0 = wid << 4;
    const int qt = blockIdx.x, bh = blockIdx.y;
    const int q0 = qt * 128;
    const size_t qkBase = (size_t)bh * SEQ * DHEAD;
    const size_t vBase  = (size_t)bh * DHEAD * SEQP;
    const float4 z4 = make_float4(0.f, 0.f, 0.f, 0.f);

    // ---- stage Q tile into sP, build persistent Q fragments ----
    #pragma unroll
    for (int i = 0; i < 8; i++) {
        const int idx = tid + (i << 8);      // 2048 float4
        const int r  = idx >> 4;
        const int c4 = (idx & 15) << 2;
        float4 v = (q0 + r < SEQ) ? *(const float4*)(gq + qkBase + (size_t)(q0 + r) * DHEAD + c4) : z4;
        *(float4*)(sP + r * 68 + c4) = v;
    }
    __syncthreads();
    uint32_t qf[8][4];
    #pragma unroll
    for (int kk = 0; kk < 8; kk++) {
        const int c = (kk << 3) + tg;
        qf[kk][0] = f2u(sP[(m0 + g) * 68 + c]);
        qf[kk][1] = f2u(sP[(m0 + g + 8) * 68 + c]);
        qf[kk][2] = f2u(sP[(m0 + g) * 68 + c + 4]);
        qf[kk][3] = f2u(sP[(m0 + g + 8) * 68 + c + 4]);
    }
    __syncthreads();

    float oa[8][4];
    #pragma unroll
    for (int nt = 0; nt < 8; nt++)
        #pragma unroll
        for (int i = 0; i < 4; i++) oa[nt][i] = 0.f;
    float rm0 = -1e30f, rm1 = -1e30f, rl0 = 0.f, rl1 = 0.f;

    for (int kt = 0; kt < NKT; kt++) {
        const int key0 = kt * 64;
        // ---- load K tile [64 keys][64] and V^T tile [64 Dh][64 keys] ----
        #pragma unroll
        for (int i = 0; i < 4; i++) {
            const int idx = tid + (i << 8);     // 1024 float4
            const int r  = idx >> 4;
            const int c4 = (idx & 15) << 2;
            float4 kv = (key0 + r < SEQ) ? *(const float4*)(gk + qkBase + (size_t)(key0 + r) * DHEAD + c4) : z4;
            *(float4*)(sK + r * 68 + c4) = kv;
            float4 vv = *(const float4*)(gvT + vBase + (size_t)r * SEQP + key0 + c4);
            *(float4*)(sV + r * 68 + c4) = vv;
        }
        __syncthreads();

        // ---- S = Q @ K^T ----
        float sa[8][4];
        #pragma unroll
        for (int nt = 0; nt < 8; nt++)
            #pragma unroll
            for (int i = 0; i < 4; i++) sa[nt][i] = 0.f;
        #pragma unroll
        for (int kk = 0; kk < 8; kk++) {
            const int c = (kk << 3) + tg;
            uint32_t bf[8][2];
            #pragma unroll
            for (int nt = 0; nt < 8; nt++) {
                bf[nt][0] = f2u(sK[((nt << 3) + g) * 68 + c]);
                bf[nt][1] = f2u(sK[((nt << 3) + g) * 68 + c + 4]);
            }
            #pragma unroll
            for (int nt = 0; nt < 8; nt++)
                MMA_TF32(sa[nt], qf[kk][0], qf[kk][1], qf[kk][2], qf[kk][3],
                         bf[nt][0], bf[nt][1]);
        }

        // ---- online softmax (rows g / g+8, quad-wide) ----
        float sm0 = -1e30f, sm1 = -1e30f;
        #pragma unroll
        for (int nt = 0; nt < 8; nt++) {
            const int kc = key0 + (nt << 3) + (tg << 1);
            sa[nt][0] = (kc     < SEQ) ? sa[nt][0] * 0.125f : -1e30f;
            sa[nt][1] = (kc + 1 < SEQ) ? sa[nt][1] * 0.125f : -1e30f;
            sa[nt][2] = (kc     < SEQ) ? sa[nt][2] * 0.125f : -1e30f;
            sa[nt][3] = (kc + 1 < SEQ) ? sa[nt][3] * 0.125f : -1e30f;
            sm0 = fmaxf(sm0, fmaxf(sa[nt][0], sa[nt][1]));
            sm1 = fmaxf(sm1, fmaxf(sa[nt][2], sa[nt][3]));
        }
        sm0 = fmaxf(sm0, __shfl_xor_sync(0xFFFFFFFFu, sm0, 1));
        sm0 = fmaxf(sm0, __shfl_xor_sync(0xFFFFFFFFu, sm0, 2));
        sm1 = fmaxf(sm1, __shfl_xor_sync(0xFFFFFFFFu, sm1, 1));
        sm1 = fmaxf(sm1, __shfl_xor_sync(0xFFFFFFFFu, sm1, 2));
        const float nm0 = fmaxf(rm0, sm0), nm1 = fmaxf(rm1, sm1);
        const float c0 = __expf(rm0 - nm0), c1 = __expf(rm1 - nm1);
        rm0 = nm0; rm1 = nm1;
        float ls0 = 0.f, ls1 = 0.f;
        #pragma unroll
        for (int nt = 0; nt < 8; nt++) {
            sa[nt][0] = __expf(sa[nt][0] - nm0);
            sa[nt][1] = __expf(sa[nt][1] - nm0);
            sa[nt][2] = __expf(sa[nt][2] - nm1);
            sa[nt][3] = __expf(sa[nt][3] - nm1);
            ls0 += sa[nt][0] + sa[nt][1];
            ls1 += sa[nt][2] + sa[nt][3];
        }
        ls0 += __shfl_xor_sync(0xFFFFFFFFu, ls0, 1);
        ls0 += __shfl_xor_sync(0xFFFFFFFFu, ls0, 2);
        ls1 += __shfl_xor_sync(0xFFFFFFFFu, ls1, 1);
        ls1 += __shfl_xor_sync(0xFFFFFFFFu, ls1, 2);
        rl0 = rl0 * c0 + ls0;
        rl1 = rl1 * c1 + ls1;
        #pragma unroll
        for (int nt = 0; nt < 8; nt++) {
            oa[nt][0] *= c0; oa[nt][1] *= c0;
            oa[nt][2] *= c1; oa[nt][3] *= c1;
        }
        // ---- store P (tf32-rounded) to sP ----
        #pragma unroll
        for (int nt = 0; nt < 8; nt++) {
            const int cc = (nt << 3) + (tg << 1);
            *(float2*)(sP + (m0 + g) * 68 + cc)     = make_float2(rtf32(sa[nt][0]), rtf32(sa[nt][1]));
            *(float2*)(sP + (m0 + g + 8) * 68 + cc) = make_float2(rtf32(sa[nt][2]), rtf32(sa[nt][3]));
        }
        __syncthreads();

        // ---- O += P @ V ----
        #pragma unroll
        for (int kk = 0; kk < 8; kk++) {
            const int c = (kk << 3) + tg;
            uint32_t af[4];
            af[0] = f2u(sP[(m0 + g) * 68 + c]);
            af[1] = f2u(sP[(m0 + g + 8) * 68 + c]);
            af[2] = f2u(sP[(m0 + g) * 68 + c + 4]);
            af[3] = f2u(sP[(m0 + g + 8) * 68 + c + 4]);
            uint32_t bf[8][2];
            #pragma unroll
            for (int nt = 0; nt < 8; nt++) {
                bf[nt][0] = f2u(sV[((nt << 3) + g) * 68 + c]);
                bf[nt][1] = f2u(sV[((nt << 3) + g) * 68 + c + 4]);
            }
            #pragma unroll
            for (int nt = 0; nt < 8; nt++)
                MMA_TF32(oa[nt], af[0], af[1], af[2], af[3], bf[nt][0], bf[nt][1]);
        }
        __syncthreads();
    }

    // ---- epilogue: O / l -> g_attn [B*SEQ][DMODEL] at head offset ----
    const float inv0 = 1.f / rl0, inv1 = 1.f / rl1;
    const int b = bh >> 4, h = bh & 15;
    const int r0 = q0 + m0 + g, r1 = r0 + 8;
    #pragma unroll
    for (int nt = 0; nt < 8; nt++) {
        const int col = h * 64 + (nt << 3) + (tg << 1);
        if (r0 < SEQ)
            *(float2*)(gattn + (size_t)(b * SEQ + r0) * DMODEL + col) =
                make_float2(oa[nt][0] * inv0, oa[nt][1] * inv0);
        if (r1 < SEQ)
            *(float2*)(gattn + (size_t)(b * SEQ + r1) * DMODEL + col) =
                make_float2(oa[nt][2] * inv1, oa[nt][3] * inv1);
    }
}

// ---------------------------------------------------------------------------
// LayerNorm (outputs tf32-rounded)
// ---------------------------------------------------------------------------
__global__ __launch_bounds__(256) void ln_kernel(
    const float* __restrict__ x, const float* __restrict__ gamma,
    const float* __restrict__ beta, float* __restrict__ xn)
{
    int row = blockIdx.x;
    int tid = threadIdx.x;
    const float4 v = ((const float4*)(x + (size_t)row * DMODEL))[tid];
    float s  = v.x + v.y + v.z + v.w;
    float ss = v.x*v.x + v.y*v.y + v.z*v.z + v.w*v.w;
    #pragma unroll
    for (int o = 16; o; o >>= 1) {
        s  += __shfl_xor_sync(0xFFFFFFFFu, s,  o);
        ss += __shfl_xor_sync(0xFFFFFFFFu, ss, o);
    }
    __shared__ float sm[8], sm2[8];
    int w = tid >> 5;
    if ((tid & 31) == 0) { sm[w] = s; sm2[w] = ss; }
    __syncthreads();
    float ts = 0.f, tss = 0.f;
    #pragma unroll
    for (int i = 0; i < 8; i++) { ts += sm[i]; tss += sm2[i]; }
    const float inv = 1.0f / DMODEL;
    float mu  = ts * inv;
    float var = tss * inv - mu * mu;
    float r = rsqrtf(var + 1e-5f);
    float4 gv = ((const float4*)gamma)[tid];
    float4 bv = ((const float4*)beta)[tid];
    float4 o;
    o.x = rtf32((v.x - mu) * r * gv.x + bv.x);
    o.y = rtf32((v.y - mu) * r * gv.y + bv.y);
    o.z = rtf32((v.z - mu) * r * gv.z + bv.z);
    o.w = rtf32((v.w - mu) * r * gv.w + bv.w);
    ((float4*)(xn + (size_t)row * DMODEL))[tid] = o;
}

// ---------------------------------------------------------------------------
// Transpose with tf32 rounding
// ---------------------------------------------------------------------------
__global__ __launch_bounds__(256) void transpose_rnd(
    const float* __restrict__ src, float* __restrict__ dst, int R, int C)
{
    __shared__ float t[32][33];
    int c0 = blockIdx.x * 32, r0 = blockIdx.y * 32;
    int x = threadIdx.x, y = threadIdx.y;
    #pragma unroll
    for (int i = 0; i < 32; i += 8) {
        int r = r0 + y + i, c = c0 + x;
        if (r < R && c < C) t[y + i][x] = src[(size_t)r * C + c];
    }
    __syncthreads();
    #pragma unroll
    for (int i = 0; i < 32; i += 8) {
        int r = c0 + y + i, c = r0 + x;
        if (r < C && c < R) dst[(size_t)r * R + c] = rtf32(t[x][y + i]);
    }
}

// ---------------------------------------------------------------------------
// RoPE + head reshape
// ---------------------------------------------------------------------------
__global__ __launch_bounds__(256) void rope_reshape(
    const float* __restrict__ qkv, float* __restrict__ gq,
    float* __restrict__ gk, float* __restrict__ gvT)
{
    const int total = NBH * SEQ * 32;
    int idx = blockIdx.x * blockDim.x + threadIdx.x;
    if (idx >= total) return;
    int i = idx & 31;
    int t = idx >> 5;
    int n = t % SEQ; t /= SEQ;
    int h = t % HEADS;
    int b = t / HEADS;
    int bh = b * HEADS + h;

    const float* base = qkv + ((size_t)(b * SEQ + n)) * QKV_COLS + h * DHEAD;
    float q1 = base[i],        q2 = base[i + 32];
    float k1 = base[1024 + i], k2 = base[1024 + i + 32];
    float v1 = base[2048 + i], v2 = base[2048 + i + 32];
    float qo1 = q1, qo2 = q2, ko1 = k1, ko2 = k2;
    if (n > 0) {
        float p = (float)(n - 1);
        float invf = exp2f(-13.287712379549449f * ((float)i * (1.0f / 32.0f)));
        float f = p * invf;
        float c = cosf(f), s = sinf(f);
        qo1 = q1 * c - q2 * s;  qo2 = q2 * c + q1 * s;
        ko1 = k1 * c - k2 * s;  ko2 = k2 * c + k1 * s;
    }
    size_t dst = ((size_t)bh * SEQ + n) * DHEAD + i;
    gq[dst] = rtf32(qo1); gq[dst + 32] = rtf32(qo2);
    gk[dst] = rtf32(ko1); gk[dst + 32] = rtf32(ko2);
    size_t vd = ((size_t)bh * DHEAD + i) * SEQP + n;
    gvT[vd] = rtf32(v1); gvT[vd + (size_t)32 * SEQP] = rtf32(v2);
}

// Zero the key-padding columns of vT (cols SEQ..SEQP-1)
__global__ void vt_pad_zero(float* __restrict__ gvT)
{
    int idx = blockIdx.x * blockDim.x + threadIdx.x;
    const int padw = SEQP - SEQ;                 // 63
    const int total = NBH * DHEAD * padw;
    if (idx >= total) return;
    int c = idx % padw;
    int r = idx / padw;
    gvT[(size_t)r * SEQP + SEQ + c] = 0.f;
}

// ---------------------------------------------------------------------------
// Launch
// ---------------------------------------------------------------------------
static float* sym_addr(const void* sym) {
    void* p = nullptr;
    cudaGetSymbolAddress(&p, sym);
    return (float*)p;
}

extern "C" void kernel_launch(void* const* d_in, const int* in_sizes, int n_in,
                              void* d_out, int out_size)
{
    const float* x     = (const float*)d_in[0];
    const float* gamma = (const float*)d_in[1];
    const float* beta  = (const float*)d_in[2];
    const float* wqkv  = (const float*)d_in[3];
    const float* wout  = (const float*)d_in[4];
    float* out = (float*)d_out;

    float* xn    = sym_addr(g_xn);
    float* qkv   = sym_addr(g_qkv);
    float* q     = sym_addr(g_q);
    float* k     = sym_addr(g_k);
    float* vT    = sym_addr(g_vT);
    float* attn  = sym_addr(g_attn);
    float* wqkvT = sym_addr(g_wqkvT);
    float* woutT = sym_addr(g_woutT);

    cudaFuncSetAttribute(gemm_tf32_mma, cudaFuncAttributeMaxDynamicSharedMemorySize, GEMM_SMEM_BYTES);
    cudaFuncSetAttribute(fused_attn, cudaFuncAttributeMaxDynamicSharedMemorySize, ATT_SMEM_BYTES);

    // 1. LayerNorm (tf32-rounded)
    ln_kernel<<<ROWS, 256>>>(x, gamma, beta, xn);
    // 2. Transpose weights to [N,K] K-major (tf32-rounded)
    transpose_rnd<<<dim3(QKV_COLS / 32, DMODEL / 32), dim3(32, 8)>>>(wqkv, wqkvT, DMODEL, QKV_COLS);
    transpose_rnd<<<dim3(DMODEL / 32, DMODEL / 32), dim3(32, 8)>>>(wout, woutT, DMODEL, DMODEL);
    // 3. QKV = xn @ w_qkv
    gemm_tf32_mma<<<dim3(QKV_COLS / 128, (ROWS + 127) / 128), 256, GEMM_SMEM_BYTES>>>(
        xn, wqkvT, qkv, ROWS, QKV_COLS, DMODEL, DMODEL, DMODEL, QKV_COLS);
    // 4. RoPE + reshape (q,k rounded; v transposed+padded)
    {
        int total = NBH * SEQ * 32;
        rope_reshape<<<(total + 255) / 256, 256>>>(qkv, q, k, vT);
        int padtot = NBH * DHEAD * (SEQP - SEQ);
        vt_pad_zero<<<(padtot + 255) / 256, 256>>>(vT);
    }
    // 5. Fused flash attention -> attn [B*SEQ][DMODEL]
    fused_attn<<<dim3((SEQ + 127) / 128, NBH), 256, ATT_SMEM_BYTES>>>(q, k, vT, attn);
    // 6. out = attn @ w_out
    gemm_tf32_mma<<<dim3(DMODEL / 128, (ROWS + 127) / 128), 256, GEMM_SMEM_BYTES>>>(
        attn, woutT, out, ROWS, DMODEL, DMODEL, DMODEL, DMODEL, DMODEL);
}